// round 15
// baseline (speedup 1.0000x reference)
#include <cuda_runtime.h>
#include <cuda_bf16.h>
#include <cstdint>
#include <math.h>

// ---------------------------------------------------------------------------
// GraphEncoder: featurize -> 3x GAT layer -> segment-max readout -> MLP heads
// GAT GEMMs: HMMA bf16 3-term split (fp32 emulation), BM=128/BN=256, 512 thr,
// fused attention epilogue. k_agg: predicated 8x unroll (MLP=8).
// ---------------------------------------------------------------------------

#define MAXN 50000
#define MAXNP 50048
#define MAXE 800000
#define MAXB 500
#define NH 4
#define NF 64
#define HF 256
#define GW 832
#define SLOPE 0.2f

__device__ float g_h[MAXN * HF];
__device__ float g_as[MAXN * NH];
__device__ float g_ad[MAXN * NH];
__device__ int   g_cnt[MAXN];
__device__ int   g_off[MAXN + 8];
__device__ int   g_curs[MAXN];
__device__ int   g_part[128];
__device__ int   g_esrc[MAXE + MAXN];
__device__ float g_gemb[MAXB * GW];
__device__ float g_lat[MAXB * HF];
__device__ __nv_bfloat16 g_asp[(size_t)MAXNP * 768];   // split A  [Npad, 3K]
__device__ __nv_bfloat16 g_bsp[256 * 768];             // split W^T [256, 3K]

// ======================= PTX helpers ============================
__device__ __forceinline__ uint32_t smem_u32(const void* p) {
    uint32_t a;
    asm("{ .reg .u64 t; cvta.to.shared.u64 t, %1; cvt.u32.u64 %0, t; }"
        : "=r"(a) : "l"(p));
    return a;
}
__device__ __forceinline__ void cp16(uint32_t s, const void* g) {
    asm volatile("cp.async.ca.shared.global [%0], [%1], 16;" :: "r"(s), "l"(g) : "memory");
}
__device__ __forceinline__ void ldm4(uint32_t* f, uint32_t a) {
    asm volatile("ldmatrix.sync.aligned.m8n8.x4.shared.b16 {%0,%1,%2,%3}, [%4];"
                 : "=r"(f[0]), "=r"(f[1]), "=r"(f[2]), "=r"(f[3]) : "r"(a));
}
__device__ __forceinline__ void mma16816(float* c, const uint32_t* a, const uint32_t* b) {
    asm volatile("mma.sync.aligned.m16n8k16.row.col.f32.bf16.bf16.f32 "
                 "{%0,%1,%2,%3}, {%4,%5,%6,%7}, {%8,%9}, {%0,%1,%2,%3};"
                 : "+f"(c[0]), "+f"(c[1]), "+f"(c[2]), "+f"(c[3])
                 : "r"(a[0]), "r"(a[1]), "r"(a[2]), "r"(a[3]), "r"(b[0]), "r"(b[1]));
}

// -------------------- small utility kernels --------------------
__global__ void k_zero_f(float* p, int n) {
    int i = blockIdx.x * blockDim.x + threadIdx.x;
    if (i < n) p[i] = 0.0f;
}
__global__ void k_set_i(int* p, int v, int n) {
    int i = blockIdx.x * blockDim.x + threadIdx.x;
    if (i < n) p[i] = v;
}

// -------------------- node featurization (writes bf16 split) ----------------
__global__ void k_featurize(const float* __restrict__ nf, const int* __restrict__ bmask,
                            const int* __restrict__ batch,
                            const float* __restrict__ bboxW, const float* __restrict__ bboxb,
                            const float* __restrict__ maskE,
                            const float* __restrict__ nodeW, const float* __restrict__ nodeb,
                            __nv_bfloat16* __restrict__ Asp, unsigned* __restrict__ g) {
    __shared__ float c[128];
    int n = blockIdx.x;
    int t = threadIdx.x;
    float x = bboxb[t];
#pragma unroll
    for (int k = 0; k < 5; k++) x += nf[n * 5 + k] * bboxW[k * 64 + t];
    c[t] = fmaxf(x, 0.0f);
    c[64 + t] = fmaxf(maskE[bmask[n] * 64 + t], 0.0f);
    __syncthreads();
    float acc = nodeb[t];
#pragma unroll 8
    for (int k = 0; k < 128; k++) acc += c[k] * nodeW[k * 64 + t];
    acc = fmaxf(acc, 0.0f);
    __nv_bfloat16 hh = __float2bfloat16(acc);
    __nv_bfloat16 ll = __float2bfloat16(acc - __bfloat162float(hh));
    size_t base = (size_t)n * 192 + t;
    Asp[base] = hh;
    Asp[base + 64] = ll;
    Asp[base + 128] = hh;
    atomicMax(&g[batch[n] * GW + t], __float_as_uint(acc));
}

// -------------------- CSR build --------------------
__global__ void k_count(const int* __restrict__ dst, int* __restrict__ cnt, int E) {
    int e = blockIdx.x * blockDim.x + threadIdx.x;
    if (e < E) atomicAdd(&cnt[dst[e]], 1);
}
__global__ void k_chunk_sum(const int* __restrict__ cnt, int* __restrict__ part, int n) {
    __shared__ int s[512];
    int t = threadIdx.x;
    int i = blockIdx.x * 512 + t;
    s[t] = (i < n) ? cnt[i] : 0;
    __syncthreads();
    for (int st = 256; st > 0; st >>= 1) {
        if (t < st) s[t] += s[t + st];
        __syncthreads();
    }
    if (t == 0) part[blockIdx.x] = s[0];
}
__global__ void k_scan_part(int* part, int np) {
    __shared__ int s[128];
    int t = threadIdx.x;
    int v = (t < np) ? part[t] : 0;
    s[t] = v;
    __syncthreads();
    for (int st = 1; st < 128; st <<= 1) {
        int a = (t >= st) ? s[t - st] : 0;
        __syncthreads();
        s[t] += a;
        __syncthreads();
    }
    if (t < np) part[t] = s[t] - v;
}
// chunk scan + self-loop emission + cursor init (curs = off+1, esrc[off] = n)
__global__ void k_chunk_scan(const int* __restrict__ cnt, const int* __restrict__ part,
                             int* __restrict__ off, int* __restrict__ curs,
                             int* __restrict__ esrc, int n) {
    __shared__ int s[512];
    int t = threadIdx.x;
    int i = blockIdx.x * 512 + t;
    int v = (i < n) ? cnt[i] : 0;
    s[t] = v;
    __syncthreads();
    for (int st = 1; st < 512; st <<= 1) {
        int a = (t >= st) ? s[t - st] : 0;
        __syncthreads();
        s[t] += a;
        __syncthreads();
    }
    int base = part[blockIdx.x];
    if (i < n) {
        int o = base + s[t] - v;
        off[i] = o;
        curs[i] = o + 1;
        esrc[o] = i;            // self loop occupies slot 0 of each segment
    }
    if (i == n - 1) off[n] = base + s[t];
}
__global__ void k_scatter(const int* __restrict__ src, const int* __restrict__ dst,
                          int* __restrict__ curs, int* __restrict__ esrc, int E) {
    int e = blockIdx.x * blockDim.x + threadIdx.x;
    if (e < E) {
        int p = atomicAdd(&curs[dst[e]], 1);
        esrc[p] = src[e];
    }
}

// -------------------- W split: B'' rows n = [Wh | Wh | Wl] ------------------
__global__ void k_wsplit(const float* __restrict__ W, __nv_bfloat16* __restrict__ Bsp, int K) {
    int idx = blockIdx.x * blockDim.x + threadIdx.x;
    if (idx >= K * 256) return;
    int k = idx >> 8, n = idx & 255;
    float w = W[idx];
    __nv_bfloat16 wh = __float2bfloat16(w);
    __nv_bfloat16 wl = __float2bfloat16(w - __bfloat162float(wh));
    size_t base = (size_t)n * (3 * K) + k;
    Bsp[base] = wh;
    Bsp[base + K] = wh;
    Bsp[base + 2 * K] = wl;
}

// -------------------- HMMA GEMM: C[M,256] = A''[M,K3] @ B''^T ---------------
// BM=128, BN=256, BK=32, 512 threads (16 warps: 4m x 4n), warp tile 32x64.
// 2-stage cp.async. Epilogue fuses attention dot-products (warp wn == head wn).
#define A_ST 80
#define A_BYT (128 * A_ST)        // 10240
#define B_BYT (256 * A_ST)        // 20480
#define STG (A_BYT + B_BYT)       // 30720
#define GSMEM (2 * STG)           // 61440

__global__ __launch_bounds__(512, 1) void k_hgemm(
        const __nv_bfloat16* __restrict__ A, const __nv_bfloat16* __restrict__ B,
        const float* __restrict__ att_s, const float* __restrict__ att_d,
        float* __restrict__ C, float* __restrict__ asb, float* __restrict__ adb,
        int N, int K3) {
    extern __shared__ __align__(16) char sm[];
    uint32_t sb = smem_u32(sm);
    int tid = threadIdx.x, lane = tid & 31, wid = tid >> 5;
    int wm = wid >> 2, wn = wid & 3;
    int tile0 = blockIdx.x * 128;
    int NC = K3 >> 5;

    float acc[2][8][4];
#pragma unroll
    for (int i = 0; i < 2; i++)
#pragma unroll
        for (int j = 0; j < 8; j++)
#pragma unroll
            for (int q = 0; q < 4; q++) acc[i][j][q] = 0.0f;

    // global->smem: A row=tid>>2 (16B quarter), B row=tid>>1 (32B half)
    int ra = tid >> 2, qa = tid & 3;
    int rb = tid >> 1, hb2 = tid & 1;
    const char* gA0 = (const char*)(A + (size_t)(tile0 + ra) * K3) + qa * 16;
    const char* gB0 = (const char*)(B + (size_t)rb * K3) + hb2 * 32;
    uint32_t soA = (uint32_t)ra * A_ST + qa * 16;
    uint32_t soB = (uint32_t)rb * A_ST + hb2 * 32;

    // ldmatrix thread addresses
    uint32_t a_row = wm * 32 + (lane & 15);
    uint32_t a_kb = (lane >> 4) * 16;
    uint32_t b_row = wn * 64 + ((lane >> 4) & 1) * 8 + (lane & 7);
    uint32_t b_kb = ((lane >> 3) & 1) * 16;

#define ISSUE(cc) do {                                                      \
        uint32_t ba_ = sb + ((cc) & 1) * STG;                               \
        cp16(ba_ + soA, gA0 + (size_t)(cc) * 64);                           \
        uint32_t bb_ = ba_ + A_BYT + soB;                                   \
        const char* gb_ = gB0 + (size_t)(cc) * 64;                          \
        cp16(bb_, gb_); cp16(bb_ + 16, gb_ + 16);                           \
        asm volatile("cp.async.commit_group;" ::: "memory");                \
    } while (0)

    ISSUE(0);
    for (int c = 0; c < NC; c++) {
        if (c + 1 < NC) {
            ISSUE(c + 1);
            asm volatile("cp.async.wait_group 1;" ::: "memory");
        } else {
            asm volatile("cp.async.wait_group 0;" ::: "memory");
        }
        __syncthreads();
        uint32_t sA = sb + (c & 1) * STG;
        uint32_t sB = sA + A_BYT;
#pragma unroll
        for (int ks = 0; ks < 2; ks++) {
            uint32_t af[2][4];
#pragma unroll
            for (int mt = 0; mt < 2; mt++)
                ldm4(af[mt], sA + (a_row + mt * 16) * A_ST + a_kb + ks * 32);
            uint32_t bf[8][2];
#pragma unroll
            for (int p = 0; p < 4; p++) {
                uint32_t t4[4];
                ldm4(t4, sB + (b_row + p * 16) * A_ST + b_kb + ks * 32);
                bf[p * 2][0] = t4[0]; bf[p * 2][1] = t4[1];
                bf[p * 2 + 1][0] = t4[2]; bf[p * 2 + 1][1] = t4[3];
            }
#pragma unroll
            for (int mt = 0; mt < 2; mt++)
#pragma unroll
                for (int nt = 0; nt < 8; nt++)
                    mma16816(acc[mt][nt], af[mt], bf[nt]);
        }
        __syncthreads();
    }
#undef ISSUE

    // epilogue: write C + fused attention dot-products (warp wn == head wn)
    int g = lane >> 2, tig = lane & 3;
#pragma unroll
    for (int mt = 0; mt < 2; mt++) {
        int row0 = tile0 + wm * 32 + mt * 16 + g;
        int row1 = row0 + 8;
        float s0 = 0.f, d0 = 0.f, s1 = 0.f, d1 = 0.f;
#pragma unroll
        for (int nt = 0; nt < 8; nt++) {
            int col = wn * 64 + nt * 8 + tig * 2;
            float as0 = __ldg(att_s + col), as1 = __ldg(att_s + col + 1);
            float ad0 = __ldg(att_d + col), ad1 = __ldg(att_d + col + 1);
            float c0 = acc[mt][nt][0], c1 = acc[mt][nt][1];
            float c2 = acc[mt][nt][2], c3 = acc[mt][nt][3];
            s0 += c0 * as0 + c1 * as1;
            d0 += c0 * ad0 + c1 * ad1;
            s1 += c2 * as0 + c3 * as1;
            d1 += c2 * ad0 + c3 * ad1;
            if (row0 < N)
                *(float2*)(C + (size_t)row0 * HF + col) = make_float2(c0, c1);
            if (row1 < N)
                *(float2*)(C + (size_t)row1 * HF + col) = make_float2(c2, c3);
        }
#pragma unroll
        for (int o = 1; o <= 2; o <<= 1) {
            s0 += __shfl_xor_sync(0xffffffffu, s0, o);
            d0 += __shfl_xor_sync(0xffffffffu, d0, o);
            s1 += __shfl_xor_sync(0xffffffffu, s1, o);
            d1 += __shfl_xor_sync(0xffffffffu, d1, o);
        }
        if (tig == 0) {
            if (row0 < N) { asb[row0 * 4 + wn] = s0; adb[row0 * 4 + wn] = d0; }
            if (row1 < N) { asb[row1 * 4 + wn] = s1; adb[row1 * 4 + wn] = d1; }
        }
    }
}

// -------------------- GAT aggregation (predicated 8x unroll, MLP=8) ---------
__global__ __launch_bounds__(128) void k_agg(const float* __restrict__ h,
                                             const float* __restrict__ asb,
                                             const float* __restrict__ adb,
                                             const int* __restrict__ off,
                                             const int* __restrict__ esrc,
                                             const float* __restrict__ bias,
                                             const int* __restrict__ batch,
                                             __nv_bfloat16* __restrict__ Asp,
                                             unsigned* __restrict__ g, int gcol0) {
    int n = blockIdx.x;
    int head = threadIdx.x >> 5;
    int lane = threadIdx.x & 31;
    int beg = off[n], end = off[n + 1];
    float ad = adb[n * NH + head];
    float2 acc = make_float2(0.f, 0.f);
    float sum = 0.f;
    const float2* hb = (const float2*)h;
    int co = head * 32 + lane;
    int last = end - 1;

    for (int i = beg; i < end; i += 8) {
        int idx[8];
#pragma unroll
        for (int k = 0; k < 8; k++) {
            int ii = i + k;
            idx[k] = esrc[ii < end ? ii : last];
        }
        float w[8];
#pragma unroll
        for (int k = 0; k < 8; k++) {
            float v = asb[idx[k] * NH + head] + ad;
            v = (v > 0.f) ? v : SLOPE * v;
            w[k] = (i + k < end) ? __expf(v) : 0.f;
        }
        float2 hv[8];
#pragma unroll
        for (int k = 0; k < 8; k++)
            hv[k] = hb[(size_t)idx[k] * 128 + co];
#pragma unroll
        for (int k = 0; k < 8; k++) {
            sum += w[k];
            acc.x += w[k] * hv[k].x;
            acc.y += w[k] * hv[k].y;
        }
    }
    float inv = 1.0f / sum;
    int c = head * NF + lane * 2;
    float o0 = fmaxf(acc.x * inv + bias[c], 0.f);
    float o1 = fmaxf(acc.y * inv + bias[c + 1], 0.f);
    __nv_bfloat16 h0 = __float2bfloat16(o0), h1 = __float2bfloat16(o1);
    __nv_bfloat16 l0 = __float2bfloat16(o0 - __bfloat162float(h0));
    __nv_bfloat16 l1 = __float2bfloat16(o1 - __bfloat162float(h1));
    size_t base = (size_t)n * 768 + c;
    __nv_bfloat162 hh; hh.x = h0; hh.y = h1;
    __nv_bfloat162 ll; ll.x = l0; ll.y = l1;
    *(__nv_bfloat162*)(Asp + base) = hh;
    *(__nv_bfloat162*)(Asp + base + 256) = ll;
    *(__nv_bfloat162*)(Asp + base + 512) = hh;
    int b = batch[n];
    atomicMax(&g[b * GW + gcol0 + c], __float_as_uint(o0));
    atomicMax(&g[b * GW + gcol0 + c + 1], __float_as_uint(o1));
}

// -------------------- readout MLPs --------------------
__global__ void k_agg_mlp(const float* __restrict__ g, const float* __restrict__ aggW,
                          const float* __restrict__ aggb, float* __restrict__ lat) {
    __shared__ float s[GW];
    int r = blockIdx.x, t = threadIdx.x;
    for (int i = t; i < GW; i += 256) s[i] = g[r * GW + i];
    __syncthreads();
    float acc = aggb[t];
#pragma unroll 8
    for (int k = 0; k < GW; k++) acc += s[k] * aggW[k * HF + t];
    lat[r * HF + t] = acc;
}
__global__ void k_heads(const float* __restrict__ lat, const float* __restrict__ muW,
                        const float* __restrict__ mub, const float* __restrict__ vW,
                        const float* __restrict__ vb, float* __restrict__ out, int B) {
    __shared__ float s[HF];
    int r = blockIdx.x, t = threadIdx.x;
    s[t] = lat[r * HF + t];
    __syncthreads();
    float m = mub[t], v = vb[t];
#pragma unroll 8
    for (int k = 0; k < HF; k++) {
        float x = s[k];
        m += x * muW[k * HF + t];
        v += x * vW[k * HF + t];
    }
    out[r * HF + t] = m;
    out[(size_t)B * HF + r * HF + t] = v;
}

// ---------------------------------------------------------------------------
extern "C" void kernel_launch(void* const* d_in, const int* in_sizes, int n_in,
                              void* d_out, int out_size) {
    const float* nf    = (const float*)d_in[0];
    const int*   bmask = (const int*)d_in[1];
    const int*   batch = (const int*)d_in[2];
    const int*   eidx  = (const int*)d_in[3];
    const float* bboxW = (const float*)d_in[4];
    const float* bboxb = (const float*)d_in[5];
    const float* maskE = (const float*)d_in[6];
    const float* nodeW = (const float*)d_in[7];
    const float* nodeb = (const float*)d_in[8];
    const float* w[3]  = {(const float*)d_in[9],  (const float*)d_in[13], (const float*)d_in[17]};
    const float* as_[3] = {(const float*)d_in[10], (const float*)d_in[14], (const float*)d_in[18]};
    const float* ad_[3] = {(const float*)d_in[11], (const float*)d_in[15], (const float*)d_in[19]};
    const float* bb[3] = {(const float*)d_in[12], (const float*)d_in[16], (const float*)d_in[20]};
    const float* aggW  = (const float*)d_in[21];
    const float* aggb  = (const float*)d_in[22];
    const float* muW   = (const float*)d_in[23];
    const float* mub   = (const float*)d_in[24];
    const float* vW    = (const float*)d_in[25];
    const float* vb    = (const float*)d_in[26];
    float* out = (float*)d_out;

    int N = in_sizes[0] / 5;
    int E = in_sizes[3] / 2;
    int B = out_size / (2 * HF);
    const int* src = eidx;
    const int* dst = eidx + E;

    float *hbuf, *asb, *adb, *gemb, *lat;
    int *cnt, *off, *curs, *part, *esrc;
    __nv_bfloat16 *aspb, *bspb;
    cudaGetSymbolAddress((void**)&hbuf, g_h);
    cudaGetSymbolAddress((void**)&asb, g_as);
    cudaGetSymbolAddress((void**)&adb, g_ad);
    cudaGetSymbolAddress((void**)&cnt, g_cnt);
    cudaGetSymbolAddress((void**)&off, g_off);
    cudaGetSymbolAddress((void**)&curs, g_curs);
    cudaGetSymbolAddress((void**)&part, g_part);
    cudaGetSymbolAddress((void**)&esrc, g_esrc);
    cudaGetSymbolAddress((void**)&gemb, g_gemb);
    cudaGetSymbolAddress((void**)&lat, g_lat);
    cudaGetSymbolAddress((void**)&aspb, g_asp);
    cudaGetSymbolAddress((void**)&bspb, g_bsp);

    cudaFuncSetAttribute(k_hgemm, cudaFuncAttributeMaxDynamicSharedMemorySize, GSMEM);

    int nch = (N + 511) / 512;
    int Ntiles = (N + 127) / 128;
    int gcol0[3] = {64, 64 + 256, 64 + 512};

    // Launches 1-4 ordered so ncu's capture slot (my 4th launch) = k_hgemm.
    k_zero_f<<<(B * GW + 255) / 256, 256>>>(gemb, B * GW);               // 1
    k_wsplit<<<(64 * 256 + 255) / 256, 256>>>(w[0], bspb, 64);           // 2
    k_featurize<<<N, 64>>>(nf, bmask, batch, bboxW, bboxb, maskE, nodeW, nodeb,
                           aspb, (unsigned*)gemb);                        // 3
    k_hgemm<<<Ntiles, 512, GSMEM>>>(aspb, bspb, as_[0], ad_[0], hbuf,
                                    asb, adb, N, 192);                   // 4 (profiled)
    // CSR build (self-loops emitted inside chunk_scan)
    k_set_i<<<(N + 255) / 256, 256>>>(cnt, 1, N);
    k_count<<<(E + 255) / 256, 256>>>(dst, cnt, E);
    k_chunk_sum<<<nch, 512>>>(cnt, part, N);
    k_scan_part<<<1, 128>>>(part, nch);
    k_chunk_scan<<<nch, 512>>>(cnt, part, off, curs, esrc, N);
    k_scatter<<<(E + 255) / 256, 256>>>(src, dst, curs, esrc, E);

    // layer 0 aggregation (writes split for layer 1)
    k_agg<<<N, 128>>>(hbuf, asb, adb, off, esrc, bb[0], batch, aspb,
                      (unsigned*)gemb, gcol0[0]);
    // layers 1, 2
    for (int L = 1; L < 3; L++) {
        k_wsplit<<<(256 * 256 + 255) / 256, 256>>>(w[L], bspb, 256);
        k_hgemm<<<Ntiles, 512, GSMEM>>>(aspb, bspb, as_[L], ad_[L], hbuf,
                                        asb, adb, N, 768);
        k_agg<<<N, 128>>>(hbuf, asb, adb, off, esrc, bb[L], batch, aspb,
                          (unsigned*)gemb, gcol0[L]);
    }

    k_agg_mlp<<<B, 256>>>(gemb, aggW, aggb, lat);
    k_heads<<<B, 256>>>(lat, muW, mub, vW, vb, out, B);
}

// round 17
// speedup vs baseline: 1.2666x; 1.2666x over previous
#include <cuda_runtime.h>
#include <cuda_bf16.h>
#include <cstdint>
#include <math.h>

// ---------------------------------------------------------------------------
// GraphEncoder: featurize -> 3x GAT layer -> segment-max readout -> MLP heads
// GAT GEMMs: HMMA bf16 3-term split (fp32 emulation), BM=128/BN=256, 512 thr,
// fused attention epilogue. k_agg: one warp per node, all heads per request.
// ---------------------------------------------------------------------------

#define MAXN 50000
#define MAXNP 50048
#define MAXE 800000
#define MAXB 500
#define NH 4
#define NF 64
#define HF 256
#define GW 832
#define SLOPE 0.2f

__device__ float g_h[MAXN * HF];
__device__ float g_as[MAXN * NH];
__device__ float g_ad[MAXN * NH];
__device__ int   g_cnt[MAXN];
__device__ int   g_off[MAXN + 8];
__device__ int   g_curs[MAXN];
__device__ int   g_part[128];
__device__ int   g_esrc[MAXE + MAXN];
__device__ float g_gemb[MAXB * GW];
__device__ float g_lat[MAXB * HF];
__device__ __nv_bfloat16 g_asp[(size_t)MAXNP * 768];   // split A  [Npad, 3K]
__device__ __nv_bfloat16 g_bsp[256 * 768];             // split W^T [256, 3K]

// ======================= PTX helpers ============================
__device__ __forceinline__ uint32_t smem_u32(const void* p) {
    uint32_t a;
    asm("{ .reg .u64 t; cvta.to.shared.u64 t, %1; cvt.u32.u64 %0, t; }"
        : "=r"(a) : "l"(p));
    return a;
}
__device__ __forceinline__ void cp16(uint32_t s, const void* g) {
    asm volatile("cp.async.ca.shared.global [%0], [%1], 16;" :: "r"(s), "l"(g) : "memory");
}
__device__ __forceinline__ void ldm4(uint32_t* f, uint32_t a) {
    asm volatile("ldmatrix.sync.aligned.m8n8.x4.shared.b16 {%0,%1,%2,%3}, [%4];"
                 : "=r"(f[0]), "=r"(f[1]), "=r"(f[2]), "=r"(f[3]) : "r"(a));
}
__device__ __forceinline__ void mma16816(float* c, const uint32_t* a, const uint32_t* b) {
    asm volatile("mma.sync.aligned.m16n8k16.row.col.f32.bf16.bf16.f32 "
                 "{%0,%1,%2,%3}, {%4,%5,%6,%7}, {%8,%9}, {%0,%1,%2,%3};"
                 : "+f"(c[0]), "+f"(c[1]), "+f"(c[2]), "+f"(c[3])
                 : "r"(a[0]), "r"(a[1]), "r"(a[2]), "r"(a[3]), "r"(b[0]), "r"(b[1]));
}

// -------------------- small utility kernels --------------------
__global__ void k_zero_f(float* p, int n) {
    int i = blockIdx.x * blockDim.x + threadIdx.x;
    if (i < n) p[i] = 0.0f;
}
__global__ void k_set_i(int* p, int v, int n) {
    int i = blockIdx.x * blockDim.x + threadIdx.x;
    if (i < n) p[i] = v;
}

// -------------------- node featurization (writes bf16 split) ----------------
__global__ void k_featurize(const float* __restrict__ nf, const int* __restrict__ bmask,
                            const int* __restrict__ batch,
                            const float* __restrict__ bboxW, const float* __restrict__ bboxb,
                            const float* __restrict__ maskE,
                            const float* __restrict__ nodeW, const float* __restrict__ nodeb,
                            __nv_bfloat16* __restrict__ Asp, unsigned* __restrict__ g) {
    __shared__ float c[128];
    int n = blockIdx.x;
    int t = threadIdx.x;
    float x = bboxb[t];
#pragma unroll
    for (int k = 0; k < 5; k++) x += nf[n * 5 + k] * bboxW[k * 64 + t];
    c[t] = fmaxf(x, 0.0f);
    c[64 + t] = fmaxf(maskE[bmask[n] * 64 + t], 0.0f);
    __syncthreads();
    float acc = nodeb[t];
#pragma unroll 8
    for (int k = 0; k < 128; k++) acc += c[k] * nodeW[k * 64 + t];
    acc = fmaxf(acc, 0.0f);
    __nv_bfloat16 hh = __float2bfloat16(acc);
    __nv_bfloat16 ll = __float2bfloat16(acc - __bfloat162float(hh));
    size_t base = (size_t)n * 192 + t;
    Asp[base] = hh;
    Asp[base + 64] = ll;
    Asp[base + 128] = hh;
    atomicMax(&g[batch[n] * GW + t], __float_as_uint(acc));
}

// -------------------- CSR build --------------------
__global__ void k_count(const int* __restrict__ dst, int* __restrict__ cnt, int E) {
    int e = blockIdx.x * blockDim.x + threadIdx.x;
    if (e < E) atomicAdd(&cnt[dst[e]], 1);
}
__global__ void k_chunk_sum(const int* __restrict__ cnt, int* __restrict__ part, int n) {
    __shared__ int s[512];
    int t = threadIdx.x;
    int i = blockIdx.x * 512 + t;
    s[t] = (i < n) ? cnt[i] : 0;
    __syncthreads();
    for (int st = 256; st > 0; st >>= 1) {
        if (t < st) s[t] += s[t + st];
        __syncthreads();
    }
    if (t == 0) part[blockIdx.x] = s[0];
}
__global__ void k_scan_part(int* part, int np) {
    __shared__ int s[128];
    int t = threadIdx.x;
    int v = (t < np) ? part[t] : 0;
    s[t] = v;
    __syncthreads();
    for (int st = 1; st < 128; st <<= 1) {
        int a = (t >= st) ? s[t - st] : 0;
        __syncthreads();
        s[t] += a;
        __syncthreads();
    }
    if (t < np) part[t] = s[t] - v;
}
// chunk scan + self-loop emission + cursor init (curs = off+1, esrc[off] = n)
__global__ void k_chunk_scan(const int* __restrict__ cnt, const int* __restrict__ part,
                             int* __restrict__ off, int* __restrict__ curs,
                             int* __restrict__ esrc, int n) {
    __shared__ int s[512];
    int t = threadIdx.x;
    int i = blockIdx.x * 512 + t;
    int v = (i < n) ? cnt[i] : 0;
    s[t] = v;
    __syncthreads();
    for (int st = 1; st < 512; st <<= 1) {
        int a = (t >= st) ? s[t - st] : 0;
        __syncthreads();
        s[t] += a;
        __syncthreads();
    }
    int base = part[blockIdx.x];
    if (i < n) {
        int o = base + s[t] - v;
        off[i] = o;
        curs[i] = o + 1;
        esrc[o] = i;            // self loop occupies slot 0 of each segment
    }
    if (i == n - 1) off[n] = base + s[t];
}
__global__ void k_scatter(const int* __restrict__ src, const int* __restrict__ dst,
                          int* __restrict__ curs, int* __restrict__ esrc, int E) {
    int e = blockIdx.x * blockDim.x + threadIdx.x;
    if (e < E) {
        int p = atomicAdd(&curs[dst[e]], 1);
        esrc[p] = src[e];
    }
}

// -------------------- W split: B'' rows n = [Wh | Wh | Wl] ------------------
__global__ void k_wsplit(const float* __restrict__ W, __nv_bfloat16* __restrict__ Bsp, int K) {
    int idx = blockIdx.x * blockDim.x + threadIdx.x;
    if (idx >= K * 256) return;
    int k = idx >> 8, n = idx & 255;
    float w = W[idx];
    __nv_bfloat16 wh = __float2bfloat16(w);
    __nv_bfloat16 wl = __float2bfloat16(w - __bfloat162float(wh));
    size_t base = (size_t)n * (3 * K) + k;
    Bsp[base] = wh;
    Bsp[base + K] = wh;
    Bsp[base + 2 * K] = wl;
}

// -------------------- HMMA GEMM: C[M,256] = A''[M,K3] @ B''^T ---------------
// BM=128, BN=256, BK=32, 512 threads (16 warps: 4m x 4n), warp tile 32x64.
// 2-stage cp.async. Epilogue fuses attention dot-products (warp wn == head wn).
#define A_ST 80
#define A_BYT (128 * A_ST)        // 10240
#define B_BYT (256 * A_ST)        // 20480
#define STG (A_BYT + B_BYT)       // 30720
#define GSMEM (2 * STG)           // 61440

__global__ __launch_bounds__(512, 1) void k_hgemm(
        const __nv_bfloat16* __restrict__ A, const __nv_bfloat16* __restrict__ B,
        const float* __restrict__ att_s, const float* __restrict__ att_d,
        float* __restrict__ C, float* __restrict__ asb, float* __restrict__ adb,
        int N, int K3) {
    extern __shared__ __align__(16) char sm[];
    uint32_t sb = smem_u32(sm);
    int tid = threadIdx.x, lane = tid & 31, wid = tid >> 5;
    int wm = wid >> 2, wn = wid & 3;
    int tile0 = blockIdx.x * 128;
    int NC = K3 >> 5;

    float acc[2][8][4];
#pragma unroll
    for (int i = 0; i < 2; i++)
#pragma unroll
        for (int j = 0; j < 8; j++)
#pragma unroll
            for (int q = 0; q < 4; q++) acc[i][j][q] = 0.0f;

    // global->smem: A row=tid>>2 (16B quarter), B row=tid>>1 (32B half)
    int ra = tid >> 2, qa = tid & 3;
    int rb = tid >> 1, hb2 = tid & 1;
    const char* gA0 = (const char*)(A + (size_t)(tile0 + ra) * K3) + qa * 16;
    const char* gB0 = (const char*)(B + (size_t)rb * K3) + hb2 * 32;
    uint32_t soA = (uint32_t)ra * A_ST + qa * 16;
    uint32_t soB = (uint32_t)rb * A_ST + hb2 * 32;

    // ldmatrix thread addresses
    uint32_t a_row = wm * 32 + (lane & 15);
    uint32_t a_kb = (lane >> 4) * 16;
    uint32_t b_row = wn * 64 + ((lane >> 4) & 1) * 8 + (lane & 7);
    uint32_t b_kb = ((lane >> 3) & 1) * 16;

#define ISSUE(cc) do {                                                      \
        uint32_t ba_ = sb + ((cc) & 1) * STG;                               \
        cp16(ba_ + soA, gA0 + (size_t)(cc) * 64);                           \
        uint32_t bb_ = ba_ + A_BYT + soB;                                   \
        const char* gb_ = gB0 + (size_t)(cc) * 64;                          \
        cp16(bb_, gb_); cp16(bb_ + 16, gb_ + 16);                           \
        asm volatile("cp.async.commit_group;" ::: "memory");                \
    } while (0)

    ISSUE(0);
    for (int c = 0; c < NC; c++) {
        if (c + 1 < NC) {
            ISSUE(c + 1);
            asm volatile("cp.async.wait_group 1;" ::: "memory");
        } else {
            asm volatile("cp.async.wait_group 0;" ::: "memory");
        }
        __syncthreads();
        uint32_t sA = sb + (c & 1) * STG;
        uint32_t sB = sA + A_BYT;
#pragma unroll
        for (int ks = 0; ks < 2; ks++) {
            uint32_t af[2][4];
#pragma unroll
            for (int mt = 0; mt < 2; mt++)
                ldm4(af[mt], sA + (a_row + mt * 16) * A_ST + a_kb + ks * 32);
            uint32_t bf[8][2];
#pragma unroll
            for (int p = 0; p < 4; p++) {
                uint32_t t4[4];
                ldm4(t4, sB + (b_row + p * 16) * A_ST + b_kb + ks * 32);
                bf[p * 2][0] = t4[0]; bf[p * 2][1] = t4[1];
                bf[p * 2 + 1][0] = t4[2]; bf[p * 2 + 1][1] = t4[3];
            }
#pragma unroll
            for (int mt = 0; mt < 2; mt++)
#pragma unroll
                for (int nt = 0; nt < 8; nt++)
                    mma16816(acc[mt][nt], af[mt], bf[nt]);
        }
        __syncthreads();
    }
#undef ISSUE

    // epilogue: write C + fused attention dot-products (warp wn == head wn)
    int g = lane >> 2, tig = lane & 3;
#pragma unroll
    for (int mt = 0; mt < 2; mt++) {
        int row0 = tile0 + wm * 32 + mt * 16 + g;
        int row1 = row0 + 8;
        float s0 = 0.f, d0 = 0.f, s1 = 0.f, d1 = 0.f;
#pragma unroll
        for (int nt = 0; nt < 8; nt++) {
            int col = wn * 64 + nt * 8 + tig * 2;
            float as0 = __ldg(att_s + col), as1 = __ldg(att_s + col + 1);
            float ad0 = __ldg(att_d + col), ad1 = __ldg(att_d + col + 1);
            float c0 = acc[mt][nt][0], c1 = acc[mt][nt][1];
            float c2 = acc[mt][nt][2], c3 = acc[mt][nt][3];
            s0 += c0 * as0 + c1 * as1;
            d0 += c0 * ad0 + c1 * ad1;
            s1 += c2 * as0 + c3 * as1;
            d1 += c2 * ad0 + c3 * ad1;
            if (row0 < N)
                *(float2*)(C + (size_t)row0 * HF + col) = make_float2(c0, c1);
            if (row1 < N)
                *(float2*)(C + (size_t)row1 * HF + col) = make_float2(c2, c3);
        }
#pragma unroll
        for (int o = 1; o <= 2; o <<= 1) {
            s0 += __shfl_xor_sync(0xffffffffu, s0, o);
            d0 += __shfl_xor_sync(0xffffffffu, d0, o);
            s1 += __shfl_xor_sync(0xffffffffu, s1, o);
            d1 += __shfl_xor_sync(0xffffffffu, d1, o);
        }
        if (tig == 0) {
            if (row0 < N) { asb[row0 * 4 + wn] = s0; adb[row0 * 4 + wn] = d0; }
            if (row1 < N) { asb[row1 * 4 + wn] = s1; adb[row1 * 4 + wn] = d1; }
        }
    }
}

// -------------------- GAT aggregation: one warp per node, all heads ---------
// Lane l owns channels [l*4, l*4+4) and [128+l*4, 128+l*4+4).
// Per edge: 1 esrc bcast + 1 asb float4 bcast + 2 h float4 requests.
__global__ __launch_bounds__(128) void k_agg(const float* __restrict__ h,
                                             const float* __restrict__ asb,
                                             const float* __restrict__ adb,
                                             const int* __restrict__ off,
                                             const int* __restrict__ esrc,
                                             const float* __restrict__ bias,
                                             const int* __restrict__ batch,
                                             __nv_bfloat16* __restrict__ Asp,
                                             unsigned* __restrict__ g, int gcol0,
                                             int N) {
    int n = blockIdx.x * 4 + (threadIdx.x >> 5);
    if (n >= N) return;
    int lane = threadIdx.x & 31;
    int beg = off[n], end = off[n + 1];
    bool lo = (lane < 16);             // head of group0: lo?0:1 ; group1: lo?2:3
    float4 adv = *(const float4*)(adb + n * 4);
    float adA = lo ? adv.x : adv.y;
    float adB = lo ? adv.z : adv.w;

    float4 acc0 = make_float4(0.f, 0.f, 0.f, 0.f);
    float4 acc1 = make_float4(0.f, 0.f, 0.f, 0.f);
    float sum0 = 0.f, sum1 = 0.f;
    const float4* hb = (const float4*)h;   // row = 64 float4s

#define EDGE(i_) do {                                                        \
        int s_ = esrc[i_];                                                   \
        float4 a4_ = *(const float4*)(asb + s_ * 4);                         \
        float vA_ = (lo ? a4_.x : a4_.y) + adA;                              \
        float vB_ = (lo ? a4_.z : a4_.w) + adB;                              \
        vA_ = (vA_ > 0.f) ? vA_ : SLOPE * vA_;                               \
        vB_ = (vB_ > 0.f) ? vB_ : SLOPE * vB_;                               \
        float wA_ = __expf(vA_), wB_ = __expf(vB_);                          \
        float4 x0_ = hb[(size_t)s_ * 64 + lane];                             \
        float4 x1_ = hb[(size_t)s_ * 64 + 32 + lane];                        \
        sum0 += wA_; sum1 += wB_;                                            \
        acc0.x += wA_ * x0_.x; acc0.y += wA_ * x0_.y;                        \
        acc0.z += wA_ * x0_.z; acc0.w += wA_ * x0_.w;                        \
        acc1.x += wB_ * x1_.x; acc1.y += wB_ * x1_.y;                        \
        acc1.z += wB_ * x1_.z; acc1.w += wB_ * x1_.w;                        \
    } while (0)

    int i = beg;
    for (; i + 3 < end; i += 4) {
        EDGE(i); EDGE(i + 1); EDGE(i + 2); EDGE(i + 3);
    }
    for (; i < end; i++) EDGE(i);
#undef EDGE

    float inv0 = 1.0f / sum0, inv1 = 1.0f / sum1;
    int c0 = lane * 4;
    int c1 = 128 + lane * 4;
    float4 b0 = *(const float4*)(bias + c0);
    float4 b1 = *(const float4*)(bias + c1);
    float o0[4], o1[4];
    o0[0] = fmaxf(acc0.x * inv0 + b0.x, 0.f);
    o0[1] = fmaxf(acc0.y * inv0 + b0.y, 0.f);
    o0[2] = fmaxf(acc0.z * inv0 + b0.z, 0.f);
    o0[3] = fmaxf(acc0.w * inv0 + b0.w, 0.f);
    o1[0] = fmaxf(acc1.x * inv1 + b1.x, 0.f);
    o1[1] = fmaxf(acc1.y * inv1 + b1.y, 0.f);
    o1[2] = fmaxf(acc1.z * inv1 + b1.z, 0.f);
    o1[3] = fmaxf(acc1.w * inv1 + b1.w, 0.f);

    size_t base0 = (size_t)n * 768 + c0;
    size_t base1 = (size_t)n * 768 + c1;
    __nv_bfloat162 hh, ll;
#pragma unroll
    for (int q = 0; q < 2; q++) {
        float a = o0[q * 2], bvl = o0[q * 2 + 1];
        __nv_bfloat16 ha = __float2bfloat16(a), hbv = __float2bfloat16(bvl);
        hh.x = ha; hh.y = hbv;
        ll.x = __float2bfloat16(a - __bfloat162float(ha));
        ll.y = __float2bfloat16(bvl - __bfloat162float(hbv));
        *(__nv_bfloat162*)(Asp + base0 + q * 2) = hh;
        *(__nv_bfloat162*)(Asp + base0 + 256 + q * 2) = ll;
        *(__nv_bfloat162*)(Asp + base0 + 512 + q * 2) = hh;
    }
#pragma unroll
    for (int q = 0; q < 2; q++) {
        float a = o1[q * 2], bvl = o1[q * 2 + 1];
        __nv_bfloat16 ha = __float2bfloat16(a), hbv = __float2bfloat16(bvl);
        hh.x = ha; hh.y = hbv;
        ll.x = __float2bfloat16(a - __bfloat162float(ha));
        ll.y = __float2bfloat16(bvl - __bfloat162float(hbv));
        *(__nv_bfloat162*)(Asp + base1 + q * 2) = hh;
        *(__nv_bfloat162*)(Asp + base1 + 256 + q * 2) = ll;
        *(__nv_bfloat162*)(Asp + base1 + 512 + q * 2) = hh;
    }

    int b = batch[n];
    unsigned* gg = g + b * GW + gcol0;
#pragma unroll
    for (int q = 0; q < 4; q++) {
        atomicMax(&gg[c0 + q], __float_as_uint(o0[q]));
        atomicMax(&gg[c1 + q], __float_as_uint(o1[q]));
    }
}

// -------------------- readout MLPs --------------------
__global__ void k_agg_mlp(const float* __restrict__ g, const float* __restrict__ aggW,
                          const float* __restrict__ aggb, float* __restrict__ lat) {
    __shared__ float s[GW];
    int r = blockIdx.x, t = threadIdx.x;
    for (int i = t; i < GW; i += 256) s[i] = g[r * GW + i];
    __syncthreads();
    float acc = aggb[t];
#pragma unroll 8
    for (int k = 0; k < GW; k++) acc += s[k] * aggW[k * HF + t];
    lat[r * HF + t] = acc;
}
__global__ void k_heads(const float* __restrict__ lat, const float* __restrict__ muW,
                        const float* __restrict__ mub, const float* __restrict__ vW,
                        const float* __restrict__ vb, float* __restrict__ out, int B) {
    __shared__ float s[HF];
    int r = blockIdx.x, t = threadIdx.x;
    s[t] = lat[r * HF + t];
    __syncthreads();
    float m = mub[t], v = vb[t];
#pragma unroll 8
    for (int k = 0; k < HF; k++) {
        float x = s[k];
        m += x * muW[k * HF + t];
        v += x * vW[k * HF + t];
    }
    out[r * HF + t] = m;
    out[(size_t)B * HF + r * HF + t] = v;
}

// ---------------------------------------------------------------------------
extern "C" void kernel_launch(void* const* d_in, const int* in_sizes, int n_in,
                              void* d_out, int out_size) {
    const float* nf    = (const float*)d_in[0];
    const int*   bmask = (const int*)d_in[1];
    const int*   batch = (const int*)d_in[2];
    const int*   eidx  = (const int*)d_in[3];
    const float* bboxW = (const float*)d_in[4];
    const float* bboxb = (const float*)d_in[5];
    const float* maskE = (const float*)d_in[6];
    const float* nodeW = (const float*)d_in[7];
    const float* nodeb = (const float*)d_in[8];
    const float* w[3]  = {(const float*)d_in[9],  (const float*)d_in[13], (const float*)d_in[17]};
    const float* as_[3] = {(const float*)d_in[10], (const float*)d_in[14], (const float*)d_in[18]};
    const float* ad_[3] = {(const float*)d_in[11], (const float*)d_in[15], (const float*)d_in[19]};
    const float* bb[3] = {(const float*)d_in[12], (const float*)d_in[16], (const float*)d_in[20]};
    const float* aggW  = (const float*)d_in[21];
    const float* aggb  = (const float*)d_in[22];
    const float* muW   = (const float*)d_in[23];
    const float* mub   = (const float*)d_in[24];
    const float* vW    = (const float*)d_in[25];
    const float* vb    = (const float*)d_in[26];
    float* out = (float*)d_out;

    int N = in_sizes[0] / 5;
    int E = in_sizes[3] / 2;
    int B = out_size / (2 * HF);
    const int* src = eidx;
    const int* dst = eidx + E;

    float *hbuf, *asb, *adb, *gemb, *lat;
    int *cnt, *off, *curs, *part, *esrc;
    __nv_bfloat16 *aspb, *bspb;
    cudaGetSymbolAddress((void**)&hbuf, g_h);
    cudaGetSymbolAddress((void**)&asb, g_as);
    cudaGetSymbolAddress((void**)&adb, g_ad);
    cudaGetSymbolAddress((void**)&cnt, g_cnt);
    cudaGetSymbolAddress((void**)&off, g_off);
    cudaGetSymbolAddress((void**)&curs, g_curs);
    cudaGetSymbolAddress((void**)&part, g_part);
    cudaGetSymbolAddress((void**)&esrc, g_esrc);
    cudaGetSymbolAddress((void**)&gemb, g_gemb);
    cudaGetSymbolAddress((void**)&lat, g_lat);
    cudaGetSymbolAddress((void**)&aspb, g_asp);
    cudaGetSymbolAddress((void**)&bspb, g_bsp);

    cudaFuncSetAttribute(k_hgemm, cudaFuncAttributeMaxDynamicSharedMemorySize, GSMEM);

    int nch = (N + 511) / 512;
    int Ntiles = (N + 127) / 128;
    int gcol0[3] = {64, 64 + 256, 64 + 512};

    // Launches 1-4 ordered so ncu's capture slot (my 4th launch) = k_hgemm.
    k_zero_f<<<(B * GW + 255) / 256, 256>>>(gemb, B * GW);               // 1
    k_wsplit<<<(64 * 256 + 255) / 256, 256>>>(w[0], bspb, 64);           // 2
    k_featurize<<<N, 64>>>(nf, bmask, batch, bboxW, bboxb, maskE, nodeW, nodeb,
                           aspb, (unsigned*)gemb);                        // 3
    k_hgemm<<<Ntiles, 512, GSMEM>>>(aspb, bspb, as_[0], ad_[0], hbuf,
                                    asb, adb, N, 192);                   // 4 (profiled)
    // CSR build (self-loops emitted inside chunk_scan)
    k_set_i<<<(N + 255) / 256, 256>>>(cnt, 1, N);
    k_count<<<(E + 255) / 256, 256>>>(dst, cnt, E);
    k_chunk_sum<<<nch, 512>>>(cnt, part, N);
    k_scan_part<<<1, 128>>>(part, nch);
    k_chunk_scan<<<nch, 512>>>(cnt, part, off, curs, esrc, N);
    k_scatter<<<(E + 255) / 256, 256>>>(src, dst, curs, esrc, E);

    // layer 0 aggregation (writes split for layer 1)
    k_agg<<<(N + 3) / 4, 128>>>(hbuf, asb, adb, off, esrc, bb[0], batch, aspb,
                                (unsigned*)gemb, gcol0[0], N);
    // layers 1, 2
    for (int L = 1; L < 3; L++) {
        k_wsplit<<<(256 * 256 + 255) / 256, 256>>>(w[L], bspb, 256);
        k_hgemm<<<Ntiles, 512, GSMEM>>>(aspb, bspb, as_[L], ad_[L], hbuf,
                                        asb, adb, N, 768);
        k_agg<<<(N + 3) / 4, 128>>>(hbuf, asb, adb, off, esrc, bb[L], batch, aspb,
                                    (unsigned*)gemb, gcol0[L], N);
    }

    k_agg_mlp<<<B, 256>>>(gemb, aggW, aggb, lat);
    k_heads<<<B, 256>>>(lat, muW, mub, vW, vb, out, B);
}